// round 1
// baseline (speedup 1.0000x reference)
#include <cuda_runtime.h>
#include <cstdint>

// Problem constants (fixed-shape dataset):
//   E = 100000 entities, R = 64 relations, I = O = 256 channels.
// out[e,o] = xsum[e] * sum_r (1/cs[e,r]) * Wsum[r,o]
//   Wsum[r,o] = sum_i W[r,i,o],  xsum[e] = sum_j x[e,j]
// edge_index input is unused by the reference.

#define R_DIM 64
#define O_DIM 256
#define I_DIM 256
#define E_MAX 100352

__device__ float g_Wsum[R_DIM * O_DIM];
__device__ float g_xsum[E_MAX];

// ---------------------------------------------------------------------------
// Kernel 1: Wsum[r,o] = sum_i W[r*I*O + i*O + o]
// grid = R_DIM blocks, 256 threads (one per o). Coalesced over o.
// ---------------------------------------------------------------------------
__global__ void wsum_kernel(const float* __restrict__ W) {
    int r = blockIdx.x;
    int o = threadIdx.x;
    const float* base = W + (size_t)r * (I_DIM * O_DIM) + o;
    float s0 = 0.f, s1 = 0.f, s2 = 0.f, s3 = 0.f;
#pragma unroll 4
    for (int i = 0; i < I_DIM; i += 4) {
        s0 += base[(i + 0) * O_DIM];
        s1 += base[(i + 1) * O_DIM];
        s2 += base[(i + 2) * O_DIM];
        s3 += base[(i + 3) * O_DIM];
    }
    g_Wsum[r * O_DIM + o] = (s0 + s1) + (s2 + s3);
}

// ---------------------------------------------------------------------------
// Kernel 2: xsum[e] = sum_j x[e,j]. One warp per entity, float4 loads.
// ---------------------------------------------------------------------------
__global__ void xsum_kernel(const float* __restrict__ x, int E) {
    int warp = (blockIdx.x * blockDim.x + threadIdx.x) >> 5;
    int lane = threadIdx.x & 31;
    if (warp >= E) return;
    const float4* p = (const float4*)(x + (size_t)warp * I_DIM);
    float4 a = p[lane];
    float4 b = p[lane + 32];
    float s = (a.x + a.y) + (a.z + a.w) + (b.x + b.y) + (b.z + b.w);
#pragma unroll
    for (int off = 16; off; off >>= 1)
        s += __shfl_xor_sync(0xffffffffu, s, off);
    if (lane == 0) g_xsum[warp] = s;
}

// ---------------------------------------------------------------------------
// Kernel 3: main. blockDim=128, each thread owns output columns (2t, 2t+1).
// Wsum column pair held in 64 packed f32x2 registers.
// Per entity: threads 0..63 stage  xsum[e]/cs[e,r]  duplicated into a packed
// f32x2 smem ring (double buffered, one barrier per entity). Inner loop is
// 64 broadcast LDS.64 + 64 fma.rn.f32x2 per thread.
// ---------------------------------------------------------------------------
__global__ void __launch_bounds__(128, 2)
rgcn_main_kernel(const float* __restrict__ cs, float* __restrict__ out,
                 int E, int epb) {
    __shared__ unsigned long long csr2[2][R_DIM];

    const int tid = threadIdx.x;
    int e0 = blockIdx.x * epb;
    int e1 = e0 + epb;
    if (e1 > E) e1 = E;
    if (e0 >= e1) return;

    // Load this thread's Wsum column pair as packed f32x2 (bitwise identical
    // to a float2: .x in low 32 bits).
    unsigned long long w[R_DIM];
#pragma unroll
    for (int r = 0; r < R_DIM; r++) {
        w[r] = *(const unsigned long long*)(g_Wsum + r * O_DIM + 2 * tid);
    }

    // Prologue: stage entity e0 into buffer 0.
    if (tid < R_DIM) {
        float c = g_xsum[e0] / cs[(size_t)e0 * R_DIM + tid];
        unsigned long long u = (unsigned long long)__float_as_uint(c);
        csr2[0][tid] = u | (u << 32);
    }
    __syncthreads();

    for (int e = e0; e < e1; e++) {
        int buf = (e - e0) & 1;

        // Prefetch next entity's scaled reciprocal into the other buffer.
        if (tid < R_DIM && (e + 1) < e1) {
            float c = g_xsum[e + 1] / cs[(size_t)(e + 1) * R_DIM + tid];
            unsigned long long u = (unsigned long long)__float_as_uint(c);
            csr2[buf ^ 1][tid] = u | (u << 32);
        }

        unsigned long long a0 = 0ull, a1 = 0ull;
#pragma unroll
        for (int r = 0; r < R_DIM; r += 2) {
            unsigned long long c0 = csr2[buf][r];
            unsigned long long c1 = csr2[buf][r + 1];
            asm("fma.rn.f32x2 %0, %1, %2, %0;" : "+l"(a0) : "l"(w[r]),     "l"(c0));
            asm("fma.rn.f32x2 %0, %1, %2, %0;" : "+l"(a1) : "l"(w[r + 1]), "l"(c1));
        }
        unsigned long long a;
        asm("add.rn.f32x2 %0, %1, %2;" : "=l"(a) : "l"(a0), "l"(a1));

        float lo = __uint_as_float((unsigned)(a & 0xffffffffull));
        float hi = __uint_as_float((unsigned)(a >> 32));
        *(float2*)(out + (size_t)e * O_DIM + 2 * tid) = make_float2(lo, hi);

        __syncthreads();  // buffer rotation barrier (1 per entity)
    }
}

// ---------------------------------------------------------------------------
// Launch. Inputs (metadata order): x f32 (E,256), cs f32 (E,64),
// W f32 (64,256,256), edge_index i64 (unused). Output f32 (E,256).
// ---------------------------------------------------------------------------
extern "C" void kernel_launch(void* const* d_in, const int* in_sizes, int n_in,
                              void* d_out, int out_size) {
    const float* x  = (const float*)d_in[0];
    const float* cs = (const float*)d_in[1];
    const float* W  = (const float*)d_in[2];
    float* out = (float*)d_out;

    int E = in_sizes[1] / R_DIM;  // cs is (E, 64)

    // 1) Wsum
    wsum_kernel<<<R_DIM, O_DIM>>>(W);

    // 2) xsum: one warp per entity, 8 warps per block
    int xblocks = (E + 7) / 8;
    xsum_kernel<<<xblocks, 256>>>(x, E);

    // 3) main
    const int EPB = 64;
    int mblocks = (E + EPB - 1) / EPB;
    rgcn_main_kernel<<<mblocks, 128>>>(cs, out, E, EPB);
}

// round 2
// speedup vs baseline: 1.8869x; 1.8869x over previous
#include <cuda_runtime.h>
#include <cstdint>

// out[e,o] = xsum[e] * sum_r (1/cs[e,r]) * Wsum[r,o]
// E=100000, R=64, I=O=256. edge_index unused.

#define R_DIM 64
#define O_DIM 256
#define I_DIM 256
#define E_MAX 100352
#define TE    64          // entities per block in main kernel

__device__ float g_Wpart[4][R_DIM * O_DIM];
__device__ float g_Wsum[R_DIM * O_DIM];
__device__ float g_xsum[E_MAX];

// ---------------------------------------------------------------------------
// k1: partial Wsum. grid (64, 4): block (r, i-chunk of 64). 256 blocks keeps
// the chip busier than round-1's 64 (which was latency-bound at 14.6us).
// ---------------------------------------------------------------------------
__global__ void wsum_part_kernel(const float* __restrict__ W) {
    int r = blockIdx.x, c = blockIdx.y, o = threadIdx.x;
    const float* base = W + (size_t)r * (I_DIM * O_DIM) + (size_t)c * 64 * O_DIM + o;
    float s0 = 0.f, s1 = 0.f, s2 = 0.f, s3 = 0.f;
#pragma unroll
    for (int i = 0; i < 64; i += 4) {
        s0 += base[(i + 0) * O_DIM];
        s1 += base[(i + 1) * O_DIM];
        s2 += base[(i + 2) * O_DIM];
        s3 += base[(i + 3) * O_DIM];
    }
    g_Wpart[c][r * O_DIM + o] = (s0 + s1) + (s2 + s3);
}

// ---------------------------------------------------------------------------
// k2: xsum[e] = sum_j x[e,j]  (one warp per entity, 2x float4 per lane).
// First 64 blocks additionally reduce the 4 Wsum partials (16384 elems).
// ---------------------------------------------------------------------------
__global__ void xsum_reduce_kernel(const float* __restrict__ x, int E) {
    if (blockIdx.x < 64) {
        int idx = blockIdx.x * 256 + threadIdx.x;
        g_Wsum[idx] = (g_Wpart[0][idx] + g_Wpart[1][idx]) +
                      (g_Wpart[2][idx] + g_Wpart[3][idx]);
    }
    int warp = (blockIdx.x * blockDim.x + threadIdx.x) >> 5;
    int lane = threadIdx.x & 31;
    if (warp >= E) return;
    const float4* p = (const float4*)(x + (size_t)warp * I_DIM);
    float4 a = p[lane];
    float4 b = p[lane + 32];
    float s = (a.x + a.y) + (a.z + a.w) + (b.x + b.y) + (b.z + b.w);
#pragma unroll
    for (int off = 16; off; off >>= 1)
        s += __shfl_xor_sync(0xffffffffu, s, off);
    if (lane == 0) g_xsum[warp] = s;
}

// ---------------------------------------------------------------------------
// k3: main. 256 threads compute a TE(64) x 256 tile.
//  smem: w2  = Wsum packed as f32x2 col-pairs  [64][128] ull  (64 KB)
//        c2  = (xsum[e]/cs[e,r]) duplicated lo/hi [TE][64] ull (32 KB)
//  Thread (tc = tid&31, te = tid>>5): 8 entities x 4 col-pairs (8 cols).
//  Inner loop r: 2 LDS.128 + 8 broadcast LDS.64 + 32 independent FFMA2.
//  ONE __syncthreads per block.
// ---------------------------------------------------------------------------
__global__ void __launch_bounds__(256, 2)
rgcn_main_kernel(const float* __restrict__ cs, float* __restrict__ out, int E) {
    extern __shared__ unsigned long long sm[];
    unsigned long long* w2 = sm;                           // 8192 ull
    unsigned long long* c2 = sm + R_DIM * (O_DIM / 2);     // 4096 ull

    const int tid = threadIdx.x;
    const int e0 = blockIdx.x * TE;

    // Stage Wsum (already adjacent col pairs in memory -> direct ull copy).
    const unsigned long long* gw = (const unsigned long long*)g_Wsum;
#pragma unroll
    for (int k = 0; k < 32; k++)
        w2[tid + k * 256] = gw[tid + k * 256];

    // Stage scaled reciprocals, duplicated into both f32x2 lanes.
#pragma unroll
    for (int k = 0; k < 16; k++) {
        int idx = tid + k * 256;            // idx = e*64 + r, r consecutive -> coalesced cs reads
        int e = idx >> 6, r = idx & 63;
        float c = 0.f;
        if (e0 + e < E)
            c = g_xsum[e0 + e] / cs[(size_t)(e0 + e) * R_DIM + r];
        unsigned long long u = (unsigned long long)__float_as_uint(c);
        c2[idx] = u | (u << 32);
    }
    __syncthreads();

    const int tc = tid & 31;   // col group: pairs tc*4 .. tc*4+3 (cols 8tc..8tc+7)
    const int te = tid >> 5;   // entity group: entities te*8 .. te*8+7

    unsigned long long acc[8][4];
#pragma unroll
    for (int j = 0; j < 8; j++)
#pragma unroll
        for (int k = 0; k < 4; k++) acc[j][k] = 0ull;

#pragma unroll 16
    for (int r = 0; r < R_DIM; r++) {
        ulonglong2 wa = *(const ulonglong2*)&w2[r * (O_DIM / 2) + tc * 4];
        ulonglong2 wb = *(const ulonglong2*)&w2[r * (O_DIM / 2) + tc * 4 + 2];
#pragma unroll
        for (int j = 0; j < 8; j++) {
            unsigned long long cv = c2[(te * 8 + j) * R_DIM + r];  // broadcast in warp
            asm("fma.rn.f32x2 %0, %1, %2, %0;" : "+l"(acc[j][0]) : "l"(wa.x), "l"(cv));
            asm("fma.rn.f32x2 %0, %1, %2, %0;" : "+l"(acc[j][1]) : "l"(wa.y), "l"(cv));
            asm("fma.rn.f32x2 %0, %1, %2, %0;" : "+l"(acc[j][2]) : "l"(wb.x), "l"(cv));
            asm("fma.rn.f32x2 %0, %1, %2, %0;" : "+l"(acc[j][3]) : "l"(wb.y), "l"(cv));
        }
    }

    // Store: 8 consecutive floats per entity at col 8*tc (two 16B stores).
#pragma unroll
    for (int j = 0; j < 8; j++) {
        int e = e0 + te * 8 + j;
        if (e < E) {
            ulonglong2 v0; v0.x = acc[j][0]; v0.y = acc[j][1];
            ulonglong2 v1; v1.x = acc[j][2]; v1.y = acc[j][3];
            ulonglong2* dst = (ulonglong2*)(out + (size_t)e * O_DIM + tc * 8);
            dst[0] = v0;
            dst[1] = v1;
        }
    }
}

// ---------------------------------------------------------------------------
// Launch. Inputs: x f32 (E,256), cs f32 (E,64), W f32 (64,256,256),
// edge_index i64 (unused). Output f32 (E,256).
// ---------------------------------------------------------------------------
extern "C" void kernel_launch(void* const* d_in, const int* in_sizes, int n_in,
                              void* d_out, int out_size) {
    const float* x  = (const float*)d_in[0];
    const float* cs = (const float*)d_in[1];
    const float* W  = (const float*)d_in[2];
    float* out = (float*)d_out;

    int E = in_sizes[1] / R_DIM;

    static bool configured = false;
    if (!configured) {
        cudaFuncSetAttribute(rgcn_main_kernel,
                             cudaFuncAttributeMaxDynamicSharedMemorySize,
                             96 * 1024);
        configured = true;
    }

    // k1: Wsum partials
    dim3 wgrid(R_DIM, 4);
    wsum_part_kernel<<<wgrid, O_DIM>>>(W);

    // k2: xsum (+ Wsum reduce in first 64 blocks)
    int xblocks = (E + 7) / 8;                 // 8 warps/block, 1 entity/warp
    xsum_reduce_kernel<<<xblocks, 256>>>(x, E);

    // k3: main
    int mblocks = (E + TE - 1) / TE;
    rgcn_main_kernel<<<mblocks, 256, 96 * 1024>>>(cs, out, E);
}